// round 3
// baseline (speedup 1.0000x reference)
#include <cuda_runtime.h>
#include <math.h>

#define MIN_NORM 1e-15f
#define B_ 256
#define T_ 128
#define DIN_ 768
#define H_ 128
#define DOUT_ 64
#define NROWS (B_*T_)   // 32768

// ---------------- scratch (static device allocations are allowed) ----------
__device__ float g_Y[(size_t)NROWS * 384];   // GEMM out -> overwritten with Ux vectors
__device__ float g_s[NROWS];                 // tanh(un)/un
__device__ float g_xn[NROWS];                // clamp(||proj||)
__device__ float g_axn[NROWS];               // artanh(clip(xn))
__device__ float g_tn[NROWS * 3];            // ||mobius_matvec(U_g, x)|| per row/gate
__device__ float g_u[B_ * H_];
__device__ float g_v[B_ * H_];

// ---------------- helpers --------------------------------------------------
__device__ __forceinline__ float clampA(float v) {
    return fmaxf(fminf(v, 1.0f - 1e-5f), -1.0f + 1e-5f);
}
__device__ __forceinline__ float artanh_(float v) { return atanhf(clampA(v)); }

__device__ __forceinline__ float mobadd(float xj, float x2, float yj, float y2, float xy) {
    float num = (1.0f + 2.0f * xy + y2) * xj + (1.0f - x2) * yj;
    float den = 1.0f + 2.0f * xy + x2 * y2;
    return num / fmaxf(den, MIN_NORM);
}

// multi-value block reduction for blockDim.x == 128 (4 warps); returns sum in v[n] on all threads
template <int N>
__device__ __forceinline__ void red4(float* v, float* sc) {
    int wid = threadIdx.x >> 5, lane = threadIdx.x & 31;
#pragma unroll
    for (int n = 0; n < N; n++) {
        float x = v[n];
#pragma unroll
        for (int o = 16; o; o >>= 1) x += __shfl_xor_sync(0xffffffffu, x, o);
        if (lane == 0) sc[wid * N + n] = x;
    }
    __syncthreads();
#pragma unroll
    for (int n = 0; n < N; n++) v[n] = sc[n] + sc[N + n] + sc[2 * N + n] + sc[3 * N + n];
    __syncthreads();
}

// ---------------- kernel 1: per-row expmap0 stats --------------------------
__global__ void k_stats(const float* __restrict__ seq) {
    int r = blockIdx.x;
    const float* p = seq + (size_t)r * DIN_;
    float ss = 0.0f;
    for (int i = threadIdx.x; i < DIN_; i += 256) { float v = p[i]; ss = fmaf(v, v, ss); }
    __shared__ float sc[8];
    int wid = threadIdx.x >> 5, lane = threadIdx.x & 31;
#pragma unroll
    for (int o = 16; o; o >>= 1) ss += __shfl_xor_sync(0xffffffffu, ss, o);
    if (lane == 0) sc[wid] = ss;
    __syncthreads();
    if (threadIdx.x == 0) {
        float tot = 0.0f;
#pragma unroll
        for (int w = 0; w < 8; w++) tot += sc[w];
        float un = sqrtf(tot);
        float unc = fmaxf(un, MIN_NORM);
        float s = tanhf(unc) / unc;
        float xn = fmaxf(s * un, MIN_NORM);
        g_s[r] = s;
        g_xn[r] = xn;
        g_axn[r] = artanh_(xn);
    }
}

// ---------------- kernel 2: GEMM Y = seq @ [uz;ur;uh]^T --------------------
// M=32768, N=384 (gate = blockIdx.y, 128 cols each), K=768. BM=BN=128, BK=8.
__global__ __launch_bounds__(256) void k_gemm(const float* __restrict__ A,
                                              const float* __restrict__ Uz,
                                              const float* __restrict__ Ur,
                                              const float* __restrict__ Uh) {
    __shared__ float As[8 * 128];
    __shared__ float Bs[8 * 128];
    const float* Ug = (blockIdx.y == 0) ? Uz : ((blockIdx.y == 1) ? Ur : Uh);
    int tid = threadIdx.x;
    int tx = tid & 15, ty = tid >> 4;
    int row0 = blockIdx.x * 128;

    float acc[8][8];
#pragma unroll
    for (int i = 0; i < 8; i++)
#pragma unroll
        for (int j = 0; j < 8; j++) acc[i][j] = 0.0f;

    int lm = tid >> 1;            // 0..127
    int lk = (tid & 1) * 4;       // 0 or 4
    const float* Aptr = A + (size_t)(row0 + lm) * DIN_ + lk;
    const float* Bptr = Ug + (size_t)lm * DIN_ + lk;

    for (int kb = 0; kb < DIN_; kb += 8) {
        float4 av = *(const float4*)(Aptr + kb);
        float4 bv = *(const float4*)(Bptr + kb);
        __syncthreads();
        As[(lk + 0) * 128 + lm] = av.x; As[(lk + 1) * 128 + lm] = av.y;
        As[(lk + 2) * 128 + lm] = av.z; As[(lk + 3) * 128 + lm] = av.w;
        Bs[(lk + 0) * 128 + lm] = bv.x; Bs[(lk + 1) * 128 + lm] = bv.y;
        Bs[(lk + 2) * 128 + lm] = bv.z; Bs[(lk + 3) * 128 + lm] = bv.w;
        __syncthreads();
#pragma unroll
        for (int k = 0; k < 8; k++) {
            float4 a0 = *(const float4*)&As[k * 128 + ty * 4];
            float4 a1 = *(const float4*)&As[k * 128 + 64 + ty * 4];
            float4 b0 = *(const float4*)&Bs[k * 128 + tx * 4];
            float4 b1 = *(const float4*)&Bs[k * 128 + 64 + tx * 4];
            float ra[8] = {a0.x, a0.y, a0.z, a0.w, a1.x, a1.y, a1.z, a1.w};
            float rb[8] = {b0.x, b0.y, b0.z, b0.w, b1.x, b1.y, b1.z, b1.w};
#pragma unroll
            for (int i = 0; i < 8; i++)
#pragma unroll
                for (int j = 0; j < 8; j++) acc[i][j] = fmaf(ra[i], rb[j], acc[i][j]);
        }
    }
#pragma unroll
    for (int i = 0; i < 8; i++) {
        int m = row0 + ((i < 4) ? (ty * 4 + i) : (64 + ty * 4 + (i - 4)));
        float* dst = g_Y + (size_t)m * 384 + blockIdx.y * 128;
        float4 c0 = {acc[i][0], acc[i][1], acc[i][2], acc[i][3]};
        float4 c1 = {acc[i][4], acc[i][5], acc[i][6], acc[i][7]};
        *(float4*)&dst[tx * 4] = c0;
        *(float4*)&dst[64 + tx * 4] = c1;
    }
}

// ---------------- kernel 3: finalize mobius_matvec(U_g, proj) in-place -----
__global__ __launch_bounds__(128) void k_fin() {
    int r = blockIdx.x, j = threadIdx.x;
    float s = g_s[r], xn = g_xn[r], axn = g_axn[r];
    __shared__ float sc[4];
    float* Yr = g_Y + (size_t)r * 384;
#pragma unroll
    for (int g = 0; g < 3; g++) {
        float y = Yr[g * 128 + j];
        float v[1] = {y * y};
        red4<1>(v, sc);
        float ny = sqrtf(v[0]);
        float mxn = fmaxf(s * ny, MIN_NORM);
        float t = tanhf(mxn / xn * axn);
        Yr[g * 128 + j] = t * s * y / mxn;
        if (j == 0) g_tn[r * 3 + g] = t;
    }
}

// ---------------- kernel 4: recurrence (1 batch / CTA, weights in smem) ----
__global__ __launch_bounds__(128) void k_rec(const float* __restrict__ wz,
                                             const float* __restrict__ wr,
                                             const float* __restrict__ wh,
                                             const float* __restrict__ bz,
                                             const float* __restrict__ br,
                                             const float* __restrict__ bh,
                                             const float* __restrict__ mask1,
                                             const float* __restrict__ mask2) {
    extern __shared__ float smem[];
    float* sWz = smem;                 // [k*128+j] transposed
    float* sWr = smem + 16384;
    float* sWh = smem + 32768;
    float* sh_h = smem + 49152;        // 128
    float* sh_rh = sh_h + 128;         // 128
    float* sc = sh_rh + 128;           // 16

    int b = blockIdx.x, j = threadIdx.x;
    for (int idx = j; idx < 16384; idx += 128) {
        int row = idx >> 7, k = idx & 127;
        sWz[k * 128 + row] = wz[idx];
        sWr[k * 128 + row] = wr[idx];
        sWh[k * 128 + row] = wh[idx];
    }
    float bzj = bz[j], brj = br[j], bhj = bh[j];
    sh_h[j] = 0.0f;
    __syncthreads();

    float vals[4];
    vals[0] = bzj * bzj; vals[1] = brj * brj; vals[2] = bhj * bhj;
    red4<3>(vals, sc);
    float nb2z = vals[0], nb2r = vals[1], nb2h = vals[2];

    float hj = 0.0f, hn2 = 0.0f;
    float hn = MIN_NORM, ahn = artanh_(MIN_NORM);
    float uacc = 0.0f, vacc = 0.0f;

    for (int t = 0; t < T_; t++) {
        int r = b * T_ + t;
        const float* ux = g_Y + (size_t)r * 384;
        float uxz = ux[j], uxr = ux[128 + j], uxh = ux[256 + j];
        float tzu = g_tn[r * 3 + 0], tru = g_tn[r * 3 + 1], thu = g_tn[r * 3 + 2];

        // W_z h, W_r h
        float az = 0.0f, ar = 0.0f;
#pragma unroll 8
        for (int k = 0; k < 128; k++) {
            float hk = sh_h[k];
            az = fmaf(sWz[k * 128 + j], hk, az);
            ar = fmaf(sWr[k * 128 + j], hk, ar);
        }
        vals[0] = az * az; vals[1] = ar * ar; red4<2>(vals, sc);
        float mz = fmaxf(sqrtf(vals[0]), MIN_NORM);
        float mr = fmaxf(sqrtf(vals[1]), MIN_NORM);
        float tz = tanhf(mz / hn * ahn), tr = tanhf(mr / hn * ahn);
        float m1z = tz * az / mz, m1r = tr * ar / mr;

        vals[0] = m1z * uxz; vals[1] = m1r * uxr; red4<2>(vals, sc);
        float a1z = mobadd(m1z, tz * tz, uxz, tzu * tzu, vals[0]);
        float a1r = mobadd(m1r, tr * tr, uxr, tru * tru, vals[1]);

        vals[0] = a1z * a1z; vals[1] = a1z * bzj;
        vals[2] = a1r * a1r; vals[3] = a1r * brj;
        red4<4>(vals, sc);
        float trz = mobadd(a1z, vals[0], bzj, nb2z, vals[1]);
        float trr = mobadd(a1r, vals[2], brj, nb2r, vals[3]);

        vals[0] = trz * trz; vals[1] = trr * trr; red4<2>(vals, sc);
        float nzt = fmaxf(sqrtf(vals[0]), MIN_NORM);
        float nrt = fmaxf(sqrtf(vals[1]), MIN_NORM);
        float zj = 1.0f / (1.0f + expf(-(artanh_(nzt) / nzt * trz)));
        float rj = 1.0f / (1.0f + expf(-(artanh_(nrt) / nrt * trr)));

        // rh = mobius_pointwise_mul(h, r): x = r
        float hr = hj * rj;
        vals[0] = rj * rj; vals[1] = hr * hr; vals[2] = zj * zj; red4<3>(vals, sc);
        float rn = fmaxf(sqrtf(vals[0]), MIN_NORM);
        float wxn = fmaxf(sqrtf(vals[1]), MIN_NORM);
        float zn2 = vals[2];
        float t5 = tanhf(wxn / rn * artanh_(rn));
        float rhj = t5 * hr / wxn;
        sh_rh[j] = rhj;
        __syncthreads();

        // W_h rh
        float ah = 0.0f;
#pragma unroll 8
        for (int k = 0; k < 128; k++) ah = fmaf(sWh[k * 128 + j], sh_rh[k], ah);
        vals[0] = ah * ah; red4<1>(vals, sc);
        float mh = fmaxf(sqrtf(vals[0]), MIN_NORM);
        float rhn = fmaxf(t5, MIN_NORM);
        float tmh = tanhf(mh / rhn * artanh_(rhn));
        float m1h = tmh * ah / mh;

        vals[0] = m1h * uxh; red4<1>(vals, sc);
        float a1h = mobadd(m1h, tmh * tmh, uxh, thu * thu, vals[0]);

        vals[0] = a1h * a1h; vals[1] = a1h * bhj; red4<2>(vals, sc);
        float htj = mobadd(a1h, vals[0], bhj, nb2h, vals[1]);

        // delta = mobius_add(-h, h_tilde)
        vals[0] = htj * htj; vals[1] = hj * htj; red4<2>(vals, sc);
        float dj = mobadd(-hj, hn2, htj, vals[0], -vals[1]);

        // pw = mobius_pointwise_mul(delta, z): x = z
        float dz = dj * zj;
        vals[0] = dz * dz; red4<1>(vals, sc);
        float znc = fmaxf(sqrtf(zn2), MIN_NORM);
        float wxn2 = fmaxf(sqrtf(vals[0]), MIN_NORM);
        float tpw = tanhf(wxn2 / znc * artanh_(znc));
        float pwj = tpw * dz / wxn2;

        vals[0] = hj * pwj; red4<1>(vals, sc);
        float hnew = mobadd(hj, hn2, pwj, tpw * tpw, vals[0]);

        vals[0] = hnew * hnew; red4<1>(vals, sc);
        hn2 = vals[0];
        hn = fmaxf(sqrtf(hn2), MIN_NORM);
        ahn = artanh_(hn);
        hj = hnew;
        sh_h[j] = hj;
        float m1v = mask1[r], m2v = mask2[r];
        uacc = fmaf(m1v, hj, uacc);
        vacc = fmaf(m2v, hj, vacc);
        __syncthreads();
    }
    g_u[b * H_ + j] = uacc;
    g_v[b * H_ + j] = vacc;
}

// ---------------- kernel 5: epilogue (FF + dist + MLR), 1 batch / CTA ------
__global__ __launch_bounds__(128) void k_epi(const float* __restrict__ Wfu,
                                             const float* __restrict__ Wfv,
                                             const float* __restrict__ bff,
                                             const float* __restrict__ bffd,
                                             const float* __restrict__ Wfc,
                                             const float* __restrict__ p_mlr,
                                             const float* __restrict__ a_mlr,
                                             const int* __restrict__ cids,
                                             const float* __restrict__ cs_emb,
                                             float* __restrict__ out) {
    __shared__ float sh_u[128], sh_v[128], sh_c[64], sc[16];
    int b = blockIdx.x, j = threadIdx.x;
    bool lo = (j < 64);
    float uj = g_u[b * H_ + j], vj = g_v[b * H_ + j];
    sh_u[j] = uj; sh_v[j] = vj;
    int cid = cids[b];
    float bffj = lo ? bff[j] : 0.0f;
    float bffdj = lo ? bffd[j] : 0.0f;
    float cj = lo ? cs_emb[cid * 64 + j] : 0.0f;
    if (lo) sh_c[j] = cj;
    __syncthreads();

    float vals[4];
    vals[0] = uj * uj; vals[1] = vj * vj; vals[2] = uj * vj; vals[3] = bffj * bffj;
    red4<4>(vals, sc);
    float un2 = vals[0], vn2 = vals[1], uv = vals[2], nbff2 = vals[3];

    // matvecs W_ff_u @ u, W_ff_v @ v
    float mxu = 0.0f, mxv = 0.0f;
    if (lo) {
        const float* ru = Wfu + j * 128;
        const float* rv = Wfv + j * 128;
#pragma unroll 4
        for (int k = 0; k < 128; k++) {
            mxu = fmaf(ru[k], sh_u[k], mxu);
            mxv = fmaf(rv[k], sh_v[k], mxv);
        }
    }
    vals[0] = mxu * mxu; vals[1] = mxv * mxv; vals[2] = bffdj * bffdj;
    red4<3>(vals, sc);
    float nbffd2 = vals[2];
    float unc = fmaxf(sqrtf(un2), MIN_NORM), vnc = fmaxf(sqrtf(vn2), MIN_NORM);
    float mun = fmaxf(sqrtf(vals[0]), MIN_NORM), mvn = fmaxf(sqrtf(vals[1]), MIN_NORM);
    float tu = tanhf(mun / unc * artanh_(unc));
    float tv = tanhf(mvn / vnc * artanh_(vnc));
    float Mu = tu * mxu / mun, Mv = tv * mxv / mvn;

    vals[0] = Mu * Mv; red4<1>(vals, sc);
    float o1 = mobadd(Mu, tu * tu, Mv, tv * tv, vals[0]);

    vals[0] = o1 * o1; vals[1] = o1 * bffj; red4<2>(vals, sc);
    float o2 = mobadd(o1, vals[0], bffj, nbff2, vals[1]);

    // dist(u, v) over 128 dims
    float ddj = mobadd(-uj, un2, vj, vn2, -uv);
    vals[0] = ddj * ddj; red4<1>(vals, sc);
    float dist = 2.0f * artanh_(sqrtf(vals[0]));

    float bdn = fmaxf(sqrtf(nbffd2), MIN_NORM);
    float tsm = tanhf(dist * artanh_(bdn));
    float smj = tsm * bffdj / bdn;
    vals[0] = o2 * o2; vals[1] = o2 * smj; red4<2>(vals, sc);
    float o3 = mobadd(o2, vals[0], smj, tsm * tsm, vals[1]);

    // common matvec W_ff_common @ common
    float mxc = 0.0f;
    if (lo) {
        const float* rc = Wfc + j * 64;
#pragma unroll 4
        for (int k = 0; k < 64; k++) mxc = fmaf(rc[k], sh_c[k], mxc);
    }
    vals[0] = mxc * mxc; vals[1] = cj * cj; red4<2>(vals, sc);
    float mcn = fmaxf(sqrtf(vals[0]), MIN_NORM);
    float ncn = fmaxf(sqrtf(vals[1]), MIN_NORM);
    float tc = tanhf(mcn / ncn * artanh_(ncn));
    float Mc = tc * mxc / mcn;

    vals[0] = o3 * o3; vals[1] = o3 * Mc; red4<2>(vals, sc);
    float o4 = mobadd(o3, vals[0], Mc, tc * tc, vals[1]);

    // logmap0 then expmap0
    vals[0] = o4 * o4; red4<1>(vals, sc);
    float xn4 = fmaxf(sqrtf(vals[0]), MIN_NORM);
    float Lj = artanh_(xn4) / xn4 * o4;
    vals[0] = Lj * Lj; red4<1>(vals, sc);
    float uln = fmaxf(sqrtf(vals[0]), MIN_NORM);
    float oj = tanhf(uln) * Lj / uln;
    vals[0] = oj * oj; red4<1>(vals, sc);
    float nout2 = vals[0];

    // hyperbolic MLR
    for (int c = 0; c < 4; c++) {
        float pj = lo ? p_mlr[c * 64 + j] : 0.0f;
        float aj = lo ? a_mlr[c * 64 + j] : 0.0f;
        vals[0] = pj * pj; vals[1] = pj * oj; vals[2] = aj * aj;
        red4<3>(vals, sc);
        float na2 = vals[2];
        float mpx = mobadd(-pj, vals[0], oj, nout2, -vals[1]);
        vals[0] = mpx * mpx; vals[1] = mpx * aj;
        red4<2>(vals, sc);
        float lam = 2.0f / (1.0f - vals[0]);
        float na = sqrtf(na2);
        float pxa = vals[1] / fmaxf(na, 1e-12f);
        if (j == 0) out[b * 4 + c] = 2.0f * na * asinhf(pxa * lam);
    }
}

// ---------------- launcher --------------------------------------------------
extern "C" void kernel_launch(void* const* d_in, const int* in_sizes, int n_in,
                              void* d_out, int out_size) {
    const float* seq   = (const float*)d_in[0];
    const float* mask1 = (const float*)d_in[1];
    const float* mask2 = (const float*)d_in[2];
    const int*   cids  = (const int*)d_in[3];
    const float* cs    = (const float*)d_in[4];
    const float* wz = (const float*)d_in[5];
    const float* wr = (const float*)d_in[6];
    const float* wh = (const float*)d_in[7];
    const float* uz = (const float*)d_in[8];
    const float* ur = (const float*)d_in[9];
    const float* uh = (const float*)d_in[10];
    const float* bz = (const float*)d_in[11];
    const float* br = (const float*)d_in[12];
    const float* bh = (const float*)d_in[13];
    const float* Wfu = (const float*)d_in[14];
    const float* Wfv = (const float*)d_in[15];
    const float* bff = (const float*)d_in[16];
    const float* bffd = (const float*)d_in[17];
    const float* Wfc = (const float*)d_in[18];
    const float* pml = (const float*)d_in[19];
    const float* aml = (const float*)d_in[20];
    float* out = (float*)d_out;

    k_stats<<<NROWS, 256>>>(seq);
    k_gemm<<<dim3(NROWS / 128, 3), 256>>>(seq, uz, ur, uh);
    k_fin<<<NROWS, 128>>>();

    size_t shmem = (size_t)(3 * 16384 + 128 + 128 + 16) * sizeof(float); // ~193 KB
    cudaFuncSetAttribute(k_rec, cudaFuncAttributeMaxDynamicSharedMemorySize, (int)shmem);
    k_rec<<<B_, 128, shmem>>>(wz, wr, wh, bz, br, bh, mask1, mask2);

    k_epi<<<B_, 128>>>(Wfu, Wfv, bff, bffd, Wfc, pml, aml, cids, cs, out);
}

// round 5
// speedup vs baseline: 1.6214x; 1.6214x over previous
#include <cuda_runtime.h>
#include <math.h>

#define MIN_NORM 1e-15f
#define B_ 256
#define T_ 128
#define DIN_ 768
#define H_ 128
#define DOUT_ 64
#define NROWS (B_*T_)   // 32768
#define WPAD 129        // padded row stride for transposed weights in smem

// ---------------- scratch ---------------------------------------------------
__device__ float g_Y[(size_t)NROWS * 384];   // finalized mobius_matvec(U_g, proj)
__device__ float g_s[NROWS];                 // tanh(un)/un
__device__ float g_xn[NROWS];                // clamp(||proj||)
__device__ float g_axn[NROWS];               // artanh(clip(xn))
__device__ float g_tn[NROWS * 3];            // ||mobius_matvec(U_g, x)||
__device__ float g_u[B_ * H_];
__device__ float g_v[B_ * H_];

// ---------------- helpers ---------------------------------------------------
__device__ __forceinline__ float clampA(float v) {
    return fmaxf(fminf(v, 1.0f - 1e-5f), -1.0f + 1e-5f);
}
__device__ __forceinline__ float artanh_(float v) { return atanhf(clampA(v)); }

__device__ __forceinline__ float mobadd(float xj, float x2, float yj, float y2, float xy) {
    float num = (1.0f + 2.0f * xy + y2) * xj + (1.0f - x2) * yj;
    float den = 1.0f + 2.0f * xy + x2 * y2;
    return num / fmaxf(den, MIN_NORM);
}

__device__ __forceinline__ void gbar(int id) {
    asm volatile("bar.sync %0, 128;" :: "r"(id) : "memory");
}

// group reduction over 128 threads (4 warps); named barrier, no trailing bar
// (callers alternate scratch buffers so reuse is fenced by the next gbar)
template <int N>
__device__ __forceinline__ void gred(float* v, float* buf, int barid) {
    int wig = (threadIdx.x >> 5) & 3, lane = threadIdx.x & 31;
#pragma unroll
    for (int n = 0; n < N; n++) {
        float x = v[n];
#pragma unroll
        for (int o = 16; o; o >>= 1) x += __shfl_xor_sync(0xffffffffu, x, o);
        if (lane == 0) buf[wig * N + n] = x;
    }
    gbar(barid);
#pragma unroll
    for (int n = 0; n < N; n++) v[n] = buf[n] + buf[N + n] + buf[2 * N + n] + buf[3 * N + n];
}

// block reduction for 128-thread CTAs (epilogue)
template <int N>
__device__ __forceinline__ void red4(float* v, float* sc) {
    int wid = threadIdx.x >> 5, lane = threadIdx.x & 31;
#pragma unroll
    for (int n = 0; n < N; n++) {
        float x = v[n];
#pragma unroll
        for (int o = 16; o; o >>= 1) x += __shfl_xor_sync(0xffffffffu, x, o);
        if (lane == 0) sc[wid * N + n] = x;
    }
    __syncthreads();
#pragma unroll
    for (int n = 0; n < N; n++) v[n] = sc[n] + sc[N + n] + sc[2 * N + n] + sc[3 * N + n];
    __syncthreads();
}

// ---------------- kernel 1: per-row expmap0 stats ---------------------------
__global__ void k_stats(const float* __restrict__ seq) {
    int r = blockIdx.x;
    const float* p = seq + (size_t)r * DIN_;
    float ss = 0.0f;
    for (int i = threadIdx.x; i < DIN_; i += 256) { float v = p[i]; ss = fmaf(v, v, ss); }
    __shared__ float sc[8];
    int wid = threadIdx.x >> 5, lane = threadIdx.x & 31;
#pragma unroll
    for (int o = 16; o; o >>= 1) ss += __shfl_xor_sync(0xffffffffu, ss, o);
    if (lane == 0) sc[wid] = ss;
    __syncthreads();
    if (threadIdx.x == 0) {
        float tot = 0.0f;
#pragma unroll
        for (int w = 0; w < 8; w++) tot += sc[w];
        float un = sqrtf(tot);
        float unc = fmaxf(un, MIN_NORM);
        float s = tanhf(unc) / unc;
        float xn = fmaxf(s * un, MIN_NORM);
        g_s[r] = s;
        g_xn[r] = xn;
        g_axn[r] = artanh_(xn);
    }
}

// ---------------- kernel 2: GEMM + fused mobius finalize --------------------
// Y = seq @ U_g^T, per-row norm reduced via 16-lane shuffles, scaled in epilogue.
__global__ __launch_bounds__(256) void k_gemm(const float* __restrict__ A,
                                              const float* __restrict__ Uz,
                                              const float* __restrict__ Ur,
                                              const float* __restrict__ Uh) {
    __shared__ float As[2][8 * 128];
    __shared__ float Bs[2][8 * 128];
    int gate = blockIdx.y;
    const float* Ug = (gate == 0) ? Uz : ((gate == 1) ? Ur : Uh);
    int tid = threadIdx.x;
    int tx = tid & 15, ty = tid >> 4;
    int row0 = blockIdx.x * 128;

    float acc[8][8];
#pragma unroll
    for (int i = 0; i < 8; i++)
#pragma unroll
        for (int j = 0; j < 8; j++) acc[i][j] = 0.0f;

    int lm = tid >> 1;            // 0..127
    int lk = (tid & 1) * 4;       // 0 or 4
    const float* Aptr = A + (size_t)(row0 + lm) * DIN_ + lk;
    const float* Bptr = Ug + (size_t)lm * DIN_ + lk;

    // preload tile 0
    float4 av = *(const float4*)Aptr;
    float4 bv = *(const float4*)Bptr;
    As[0][(lk + 0) * 128 + lm] = av.x; As[0][(lk + 1) * 128 + lm] = av.y;
    As[0][(lk + 2) * 128 + lm] = av.z; As[0][(lk + 3) * 128 + lm] = av.w;
    Bs[0][(lk + 0) * 128 + lm] = bv.x; Bs[0][(lk + 1) * 128 + lm] = bv.y;
    Bs[0][(lk + 2) * 128 + lm] = bv.z; Bs[0][(lk + 3) * 128 + lm] = bv.w;
    __syncthreads();

    int cur = 0;
    const int NKB = DIN_ / 8;  // 96
    for (int kb = 0; kb < NKB; kb++) {
        float4 avn, bvn;
        if (kb < NKB - 1) {
            avn = *(const float4*)(Aptr + (kb + 1) * 8);
            bvn = *(const float4*)(Bptr + (kb + 1) * 8);
        }
#pragma unroll
        for (int k = 0; k < 8; k++) {
            float4 a0 = *(const float4*)&As[cur][k * 128 + ty * 4];
            float4 a1 = *(const float4*)&As[cur][k * 128 + 64 + ty * 4];
            float4 b0 = *(const float4*)&Bs[cur][k * 128 + tx * 4];
            float4 b1 = *(const float4*)&Bs[cur][k * 128 + 64 + tx * 4];
            float ra[8] = {a0.x, a0.y, a0.z, a0.w, a1.x, a1.y, a1.z, a1.w};
            float rb[8] = {b0.x, b0.y, b0.z, b0.w, b1.x, b1.y, b1.z, b1.w};
#pragma unroll
            for (int i = 0; i < 8; i++)
#pragma unroll
                for (int j = 0; j < 8; j++) acc[i][j] = fmaf(ra[i], rb[j], acc[i][j]);
        }
        if (kb < NKB - 1) {
            int nx = cur ^ 1;
            As[nx][(lk + 0) * 128 + lm] = avn.x; As[nx][(lk + 1) * 128 + lm] = avn.y;
            As[nx][(lk + 2) * 128 + lm] = avn.z; As[nx][(lk + 3) * 128 + lm] = avn.w;
            Bs[nx][(lk + 0) * 128 + lm] = bvn.x; Bs[nx][(lk + 1) * 128 + lm] = bvn.y;
            Bs[nx][(lk + 2) * 128 + lm] = bvn.z; Bs[nx][(lk + 3) * 128 + lm] = bvn.w;
            __syncthreads();
            cur = nx;
        }
    }

    // fused finalize: row m's 128 cols live in the 16 threads sharing ty
#pragma unroll
    for (int i = 0; i < 8; i++) {
        int m_local = (i < 4) ? (ty * 4 + i) : (64 + ty * 4 + (i - 4));
        int r = row0 + m_local;
        float ss = 0.0f;
#pragma unroll
        for (int j = 0; j < 8; j++) ss = fmaf(acc[i][j], acc[i][j], ss);
#pragma unroll
        for (int o = 8; o; o >>= 1) ss += __shfl_xor_sync(0xffffffffu, ss, o);
        float s = g_s[r], xn = g_xn[r], axn = g_axn[r];
        float ny = sqrtf(ss);
        float mxn = fmaxf(s * ny, MIN_NORM);
        float tcoef = tanhf(mxn / xn * axn);
        float scl = tcoef * s / mxn;
        float* dst = g_Y + (size_t)r * 384 + gate * 128;
        float4 c0 = {acc[i][0] * scl, acc[i][1] * scl, acc[i][2] * scl, acc[i][3] * scl};
        float4 c1 = {acc[i][4] * scl, acc[i][5] * scl, acc[i][6] * scl, acc[i][7] * scl};
        *(float4*)&dst[tx * 4] = c0;
        *(float4*)&dst[64 + tx * 4] = c1;
        if (tx == 0) g_tn[r * 3 + gate] = tcoef;
    }
}

// ---------------- kernel 3: recurrence, 2 batches/CTA, shared weight reads --
__global__ __launch_bounds__(256) void k_rec(const float* __restrict__ wz,
                                             const float* __restrict__ wr,
                                             const float* __restrict__ wh,
                                             const float* __restrict__ bz,
                                             const float* __restrict__ br,
                                             const float* __restrict__ bh,
                                             const float* __restrict__ mask1,
                                             const float* __restrict__ mask2) {
    extern __shared__ float smem[];
    float* sWz = smem;                       // [k*WPAD + j], transposed, padded
    float* sWr = smem + 128 * WPAD;
    float* sWh = smem + 2 * 128 * WPAD;
    float* sh_h  = smem + 3 * 128 * WPAD;    // [2][128]
    float* sh_rh = sh_h + 256;               // [2][128]
    float* part  = sh_rh + 256;              // up to 8*128 partials
    float* scb   = part + 1024;              // [2 groups][2 bufs][16]

    int tid = threadIdx.x;
    int j = tid & 127;
    int g = tid >> 7;          // batch slot within CTA AND k-half for matvecs
    int b = blockIdx.x * 2 + g;
    int barid = g + 1;
    float* buf0 = scb + g * 32;
    float* buf1 = buf0 + 16;
    int ph = 0;
#define GRED(NN, V) do { gred<NN>(V, ph ? buf1 : buf0, barid); ph ^= 1; } while (0)

    // cooperative transposed weight load (conflict-free thanks to WPAD=129)
    for (int idx = tid; idx < 16384; idx += 256) {
        int row = idx >> 7, k = idx & 127;
        sWz[k * WPAD + row] = wz[idx];
        sWr[k * WPAD + row] = wr[idx];
        sWh[k * WPAD + row] = wh[idx];
    }
    float bzj = bz[j], brj = br[j], bhj = bh[j];
    sh_h[g * 128 + j] = 0.0f;
    __syncthreads();

    float vals[4];
    vals[0] = bzj * bzj; vals[1] = brj * brj; vals[2] = bhj * bhj;
    GRED(3, vals);
    float nb2z = vals[0], nb2r = vals[1], nb2h = vals[2];

    float hj = 0.0f, hn2 = 0.0f;
    float hn = MIN_NORM, ahn = artanh_(MIN_NORM);
    float uacc = 0.0f, vacc = 0.0f;
    const float* Yb = g_Y + (size_t)(b * T_) * 384;
    int k0 = g * 64;

    for (int t = 0; t < T_; t++) {
        int r = b * T_ + t;
        float uxz = Yb[t * 384 + j];
        float uxr = Yb[t * 384 + 128 + j];
        float uxh = Yb[t * 384 + 256 + j];
        float tzu = g_tn[r * 3 + 0], tru = g_tn[r * 3 + 1], thu = g_tn[r * 3 + 2];
        float m1v = mask1[r], m2v = mask2[r];

        __syncthreads();  // sh_h of both batches ready
        // matvec W_z h, W_r h — each weight read ONCE, applied to both batches
        float az0 = 0, az1 = 0, ar0 = 0, ar1 = 0;
#pragma unroll 8
        for (int kk = 0; kk < 64; kk++) {
            int k = k0 + kk;
            float wzv = sWz[k * WPAD + j], wrv = sWr[k * WPAD + j];
            float h0 = sh_h[k], h1 = sh_h[128 + k];
            az0 = fmaf(wzv, h0, az0); az1 = fmaf(wzv, h1, az1);
            ar0 = fmaf(wrv, h0, ar0); ar1 = fmaf(wrv, h1, ar1);
        }
        part[(g * 4 + 0) * 128 + j] = az0;
        part[(g * 4 + 1) * 128 + j] = az1;
        part[(g * 4 + 2) * 128 + j] = ar0;
        part[(g * 4 + 3) * 128 + j] = ar1;
        __syncthreads();
        float az = part[(0 + g) * 128 + j] + part[(4 + g) * 128 + j];
        float ar = part[(2 + g) * 128 + j] + part[(6 + g) * 128 + j];

        vals[0] = az * az; vals[1] = ar * ar; GRED(2, vals);
        float mz = fmaxf(sqrtf(vals[0]), MIN_NORM);
        float mr = fmaxf(sqrtf(vals[1]), MIN_NORM);
        float tz = tanhf(mz / hn * ahn), tr = tanhf(mr / hn * ahn);
        float m1z = tz * az / mz, m1r = tr * ar / mr;

        vals[0] = m1z * uxz; vals[1] = m1r * uxr; GRED(2, vals);
        float a1z = mobadd(m1z, tz * tz, uxz, tzu * tzu, vals[0]);
        float a1r = mobadd(m1r, tr * tr, uxr, tru * tru, vals[1]);

        vals[0] = a1z * a1z; vals[1] = a1z * bzj;
        vals[2] = a1r * a1r; vals[3] = a1r * brj;
        GRED(4, vals);
        float trz = mobadd(a1z, vals[0], bzj, nb2z, vals[1]);
        float trr = mobadd(a1r, vals[2], brj, nb2r, vals[3]);

        vals[0] = trz * trz; vals[1] = trr * trr; GRED(2, vals);
        float nzt = fmaxf(sqrtf(vals[0]), MIN_NORM);
        float nrt = fmaxf(sqrtf(vals[1]), MIN_NORM);
        float zj = 1.0f / (1.0f + expf(-(artanh_(nzt) / nzt * trz)));
        float rj = 1.0f / (1.0f + expf(-(artanh_(nrt) / nrt * trr)));

        float hr = hj * rj;
        vals[0] = rj * rj; vals[1] = hr * hr; vals[2] = zj * zj; GRED(3, vals);
        float rn = fmaxf(sqrtf(vals[0]), MIN_NORM);
        float wxn = fmaxf(sqrtf(vals[1]), MIN_NORM);
        float zn2 = vals[2];
        float t5 = tanhf(wxn / rn * artanh_(rn));
        float rhj = t5 * hr / wxn;
        sh_rh[g * 128 + j] = rhj;
        __syncthreads();

        // matvec W_h rh
        float ah0 = 0, ah1 = 0;
#pragma unroll 8
        for (int kk = 0; kk < 64; kk++) {
            int k = k0 + kk;
            float wv = sWh[k * WPAD + j];
            ah0 = fmaf(wv, sh_rh[k], ah0);
            ah1 = fmaf(wv, sh_rh[128 + k], ah1);
        }
        part[(g * 2 + 0) * 128 + j] = ah0;
        part[(g * 2 + 1) * 128 + j] = ah1;
        __syncthreads();
        float ah = part[g * 128 + j] + part[(2 + g) * 128 + j];

        vals[0] = ah * ah; GRED(1, vals);
        float mh = fmaxf(sqrtf(vals[0]), MIN_NORM);
        float rhn = fmaxf(t5, MIN_NORM);
        float tmh = tanhf(mh / rhn * artanh_(rhn));
        float m1h = tmh * ah / mh;

        vals[0] = m1h * uxh; GRED(1, vals);
        float a1h = mobadd(m1h, tmh * tmh, uxh, thu * thu, vals[0]);

        vals[0] = a1h * a1h; vals[1] = a1h * bhj; GRED(2, vals);
        float htj = mobadd(a1h, vals[0], bhj, nb2h, vals[1]);

        vals[0] = htj * htj; vals[1] = hj * htj; GRED(2, vals);
        float dj = mobadd(-hj, hn2, htj, vals[0], -vals[1]);

        float dz = dj * zj;
        vals[0] = dz * dz; GRED(1, vals);
        float znc = fmaxf(sqrtf(zn2), MIN_NORM);
        float wxn2 = fmaxf(sqrtf(vals[0]), MIN_NORM);
        float tpw = tanhf(wxn2 / znc * artanh_(znc));
        float pwj = tpw * dz / wxn2;

        vals[0] = hj * pwj; GRED(1, vals);
        float hnew = mobadd(hj, hn2, pwj, tpw * tpw, vals[0]);

        sh_h[g * 128 + j] = hnew;
        vals[0] = hnew * hnew; GRED(1, vals);
        hn2 = vals[0];
        hn = fmaxf(sqrtf(hn2), MIN_NORM);
        ahn = artanh_(hn);
        hj = hnew;
        uacc = fmaf(m1v, hj, uacc);
        vacc = fmaf(m2v, hj, vacc);
    }
    g_u[b * H_ + j] = uacc;
    g_v[b * H_ + j] = vacc;
#undef GRED
}

// ---------------- kernel 4: epilogue (FF + dist + MLR), 1 batch / CTA ------
__global__ __launch_bounds__(128) void k_epi(const float* __restrict__ Wfu,
                                             const float* __restrict__ Wfv,
                                             const float* __restrict__ bff,
                                             const float* __restrict__ bffd,
                                             const float* __restrict__ Wfc,
                                             const float* __restrict__ p_mlr,
                                             const float* __restrict__ a_mlr,
                                             const int* __restrict__ cids,
                                             const float* __restrict__ cs_emb,
                                             float* __restrict__ out) {
    __shared__ float sh_u[128], sh_v[128], sh_c[64], sc[16];
    int b = blockIdx.x, j = threadIdx.x;
    bool lo = (j < 64);
    float uj = g_u[b * H_ + j], vj = g_v[b * H_ + j];
    sh_u[j] = uj; sh_v[j] = vj;
    int cid = cids[b];
    float bffj = lo ? bff[j] : 0.0f;
    float bffdj = lo ? bffd[j] : 0.0f;
    float cj = lo ? cs_emb[cid * 64 + j] : 0.0f;
    if (lo) sh_c[j] = cj;
    __syncthreads();

    float vals[4];
    vals[0] = uj * uj; vals[1] = vj * vj; vals[2] = uj * vj; vals[3] = bffj * bffj;
    red4<4>(vals, sc);
    float un2 = vals[0], vn2 = vals[1], uv = vals[2], nbff2 = vals[3];

    float mxu = 0.0f, mxv = 0.0f;
    if (lo) {
        const float* ru = Wfu + j * 128;
        const float* rv = Wfv + j * 128;
#pragma unroll 4
        for (int k = 0; k < 128; k++) {
            mxu = fmaf(ru[k], sh_u[k], mxu);
            mxv = fmaf(rv[k], sh_v[k], mxv);
        }
    }
    vals[0] = mxu * mxu; vals[1] = mxv * mxv; vals[2] = bffdj * bffdj;
    red4<3>(vals, sc);
    float nbffd2 = vals[2];
    float unc = fmaxf(sqrtf(un2), MIN_NORM), vnc = fmaxf(sqrtf(vn2), MIN_NORM);
    float mun = fmaxf(sqrtf(vals[0]), MIN_NORM), mvn = fmaxf(sqrtf(vals[1]), MIN_NORM);
    float tu = tanhf(mun / unc * artanh_(unc));
    float tv = tanhf(mvn / vnc * artanh_(vnc));
    float Mu = tu * mxu / mun, Mv = tv * mxv / mvn;

    vals[0] = Mu * Mv; red4<1>(vals, sc);
    float o1 = mobadd(Mu, tu * tu, Mv, tv * tv, vals[0]);

    vals[0] = o1 * o1; vals[1] = o1 * bffj; red4<2>(vals, sc);
    float o2 = mobadd(o1, vals[0], bffj, nbff2, vals[1]);

    float ddj = mobadd(-uj, un2, vj, vn2, -uv);
    vals[0] = ddj * ddj; red4<1>(vals, sc);
    float dist = 2.0f * artanh_(sqrtf(vals[0]));

    float bdn = fmaxf(sqrtf(nbffd2), MIN_NORM);
    float tsm = tanhf(dist * artanh_(bdn));
    float smj = tsm * bffdj / bdn;
    vals[0] = o2 * o2; vals[1] = o2 * smj; red4<2>(vals, sc);
    float o3 = mobadd(o2, vals[0], smj, tsm * tsm, vals[1]);

    float mxc = 0.0f;
    if (lo) {
        const float* rc = Wfc + j * 64;
#pragma unroll 4
        for (int k = 0; k < 64; k++) mxc = fmaf(rc[k], sh_c[k], mxc);
    }
    vals[0] = mxc * mxc; vals[1] = cj * cj; red4<2>(vals, sc);
    float mcn = fmaxf(sqrtf(vals[0]), MIN_NORM);
    float ncn = fmaxf(sqrtf(vals[1]), MIN_NORM);
    float tc = tanhf(mcn / ncn * artanh_(ncn));
    float Mc = tc * mxc / mcn;

    vals[0] = o3 * o3; vals[1] = o3 * Mc; red4<2>(vals, sc);
    float o4 = mobadd(o3, vals[0], Mc, tc * tc, vals[1]);

    vals[0] = o4 * o4; red4<1>(vals, sc);
    float xn4 = fmaxf(sqrtf(vals[0]), MIN_NORM);
    float Lj = artanh_(xn4) / xn4 * o4;
    vals[0] = Lj * Lj; red4<1>(vals, sc);
    float uln = fmaxf(sqrtf(vals[0]), MIN_NORM);
    float oj = tanhf(uln) * Lj / uln;
    vals[0] = oj * oj; red4<1>(vals, sc);
    float nout2 = vals[0];

    for (int c = 0; c < 4; c++) {
        float pj = lo ? p_mlr[c * 64 + j] : 0.0f;
        float aj = lo ? a_mlr[c * 64 + j] : 0.0f;
        vals[0] = pj * pj; vals[1] = pj * oj; vals[2] = aj * aj;
        red4<3>(vals, sc);
        float na2 = vals[2];
        float mpx = mobadd(-pj, vals[0], oj, nout2, -vals[1]);
        vals[0] = mpx * mpx; vals[1] = mpx * aj;
        red4<2>(vals, sc);
        float lam = 2.0f / (1.0f - vals[0]);
        float na = sqrtf(na2);
        float pxa = vals[1] / fmaxf(na, 1e-12f);
        if (j == 0) out[b * 4 + c] = 2.0f * na * asinhf(pxa * lam);
    }
}

// ---------------- launcher ---------------------------------------------------
extern "C" void kernel_launch(void* const* d_in, const int* in_sizes, int n_in,
                              void* d_out, int out_size) {
    const float* seq   = (const float*)d_in[0];
    const float* mask1 = (const float*)d_in[1];
    const float* mask2 = (const float*)d_in[2];
    const int*   cids  = (const int*)d_in[3];
    const float* cs    = (const float*)d_in[4];
    const float* wz = (const float*)d_in[5];
    const float* wr = (const float*)d_in[6];
    const float* wh = (const float*)d_in[7];
    const float* uz = (const float*)d_in[8];
    const float* ur = (const float*)d_in[9];
    const float* uh = (const float*)d_in[10];
    const float* bz = (const float*)d_in[11];
    const float* br = (const float*)d_in[12];
    const float* bh = (const float*)d_in[13];
    const float* Wfu = (const float*)d_in[14];
    const float* Wfv = (const float*)d_in[15];
    const float* bff = (const float*)d_in[16];
    const float* bffd = (const float*)d_in[17];
    const float* Wfc = (const float*)d_in[18];
    const float* pml = (const float*)d_in[19];
    const float* aml = (const float*)d_in[20];
    float* out = (float*)d_out;

    k_stats<<<NROWS, 256>>>(seq);
    k_gemm<<<dim3(NROWS / 128, 3), 256>>>(seq, uz, ur, uh);

    size_t shmem = (size_t)(3 * 128 * WPAD + 256 + 256 + 1024 + 64) * sizeof(float); // ~204.5 KB
    cudaFuncSetAttribute(k_rec, cudaFuncAttributeMaxDynamicSharedMemorySize, (int)shmem);
    k_rec<<<B_ / 2, 256, shmem>>>(wz, wr, wh, bz, br, bh, mask1, mask2);

    k_epi<<<B_, 128>>>(Wfu, Wfv, bff, bffd, Wfc, pml, aml, cids, cs, out);
}